// round 7
// baseline (speedup 1.0000x reference)
#include <cuda_runtime.h>
#include <math.h>
#include <stdint.h>

// ============================================================================
// TemporalSamplingUpSampler — ONE fused kernel.
//
// Grid (T/1024, C/CPB). Every block:
//   1) block-parallel plan into smem (identical arithmetic to round-6):
//      softmax -> Lp, r = max(rint(Lp),0), prefix sum cum[], total, l_max;
//      then per-k  sc = lmax/Lp, tf = (lmax-Lp)/Lp  (weight hoisting).
//   2) per thread: 4 output columns -> slot (exact int mul/shift for pow2 T),
//      LDS binary search -> k, j -> weight w (one fdiv per column).
//   3) fill CPB c-rows: out[c,tt] = A[c,k]*w, broadcast A read fast path,
//      float4 evict-first stores.
//
// No intermediate arrays, no extra launches: kills the ~6us of expand +
// plan-roundtrip overhead on top of the 24.6us fill.
// ============================================================================

#define MAX_K 1024
#define CPB   16

__global__ void __launch_bounds__(256) fused_kernel(
    const float* __restrict__ L,
    const float* __restrict__ A,
    float* __restrict__ out,
    int K, int T, int C, float Tf)
{
    __shared__ float s_sc[MAX_K];       // lmax / Lp
    __shared__ float s_tf[MAX_K];       // (lmax - Lp) / Lp
    __shared__ float s_Lp[MAX_K];
    __shared__ int   s_cum[MAX_K + 1];
    __shared__ float sred[32];
    __shared__ int   sscan[32];
    __shared__ int   s_total;
    __shared__ float s_lmax;

    const int t    = threadIdx.x;
    const int lane = t & 31;
    const int warp = t >> 5;
    const int nw   = blockDim.x >> 5;                     // 8
    const int EPT  = (K + blockDim.x - 1) / blockDim.x;   // 1 for K=256
    const int base = t * EPT;

    // ---------------- plan (identical arithmetic to round-6) ----------------
    float lv[4];
#pragma unroll
    for (int i = 0; i < 4; i++) {
        int k = base + i;
        lv[i] = (i < EPT && k < K) ? __ldg(L + k) : -INFINITY;
    }

    // block max(L)
    float mx = fmaxf(fmaxf(lv[0], lv[1]), fmaxf(lv[2], lv[3]));
    for (int o = 16; o; o >>= 1) mx = fmaxf(mx, __shfl_xor_sync(0xffffffffu, mx, o));
    if (lane == 0) sred[warp] = mx;
    __syncthreads();
    if (warp == 0) {
        float v = (lane < nw) ? sred[lane] : -INFINITY;
        for (int o = 16; o; o >>= 1) v = fmaxf(v, __shfl_xor_sync(0xffffffffu, v, o));
        if (lane == 0) sred[0] = v;
    }
    __syncthreads();
    mx = sred[0];
    __syncthreads();

    // block sum(exp)
    float e[4];
    float s = 0.0f;
#pragma unroll
    for (int i = 0; i < 4; i++) {
        int k = base + i;
        e[i] = (i < EPT && k < K) ? expf(lv[i] - mx) : 0.0f;
        s += e[i];
    }
    for (int o = 16; o; o >>= 1) s += __shfl_xor_sync(0xffffffffu, s, o);
    if (lane == 0) sred[warp] = s;
    __syncthreads();
    if (warp == 0) {
        float v = (lane < nw) ? sred[lane] : 0.0f;
        for (int o = 16; o; o >>= 1) v += __shfl_xor_sync(0xffffffffu, v, o);
        if (lane == 0) sred[0] = v;
    }
    __syncthreads();
    const float sum = sred[0];
    __syncthreads();

    // Lp -> smem, r = max(rint(Lp),0), maxLp
    float maxLp = -INFINITY;
    int rr[4];
    int rs = 0;
#pragma unroll
    for (int i = 0; i < 4; i++) {
        int k = base + i;
        if (i < EPT && k < K) {
            float Lp = Tf * __fdiv_rn(e[i], sum);
            s_Lp[k] = Lp;
            maxLp = fmaxf(maxLp, Lp);
            int r = (int)rintf(Lp);        // half-to-even == np.rint
            if (r < 0) r = 0;
            rr[i] = r;
            rs += r;
        } else rr[i] = 0;
    }

    // block max(Lp)
    float mLp = maxLp;
    for (int o = 16; o; o >>= 1) mLp = fmaxf(mLp, __shfl_xor_sync(0xffffffffu, mLp, o));
    if (lane == 0) sred[warp] = mLp;
    __syncthreads();
    if (warp == 0) {
        float v = (lane < nw) ? sred[lane] : -INFINITY;
        for (int o = 16; o; o >>= 1) v = fmaxf(v, __shfl_xor_sync(0xffffffffu, v, o));
        if (lane == 0) sred[0] = v;
    }

    // block scan of rs (two-level shfl)
    int incl = rs;
    for (int o = 1; o < 32; o <<= 1) {
        int v = __shfl_up_sync(0xffffffffu, incl, o);
        if (lane >= o) incl += v;
    }
    if (lane == 31) sscan[warp] = incl;
    __syncthreads();
    if (warp == 0) {
        int v = (lane < nw) ? sscan[lane] : 0;
        for (int o = 1; o < 32; o <<= 1) {
            int u = __shfl_up_sync(0xffffffffu, v, o);
            if (lane >= o) v += u;
        }
        if (lane < nw) sscan[lane] = v;    // inclusive warp totals
    }
    __syncthreads();

    const int warp_excl = (warp == 0) ? 0 : sscan[warp - 1];
    int running = warp_excl + (incl - rs);     // exclusive prefix, this thread
#pragma unroll
    for (int i = 0; i < 4; i++) {
        int k = base + i;
        if (i < EPT && k < K) {
            running += rr[i];
            s_cum[k + 1] = running;
        }
    }
    if (t == 0) {
        s_cum[0] = 0;
        s_total  = sscan[nw - 1];
        double dm = (double)sred[0] + 0.5;
        s_lmax = (float)(long long)dm;     // int(max+0.5), trunc==floor (>=0)
    }
    __syncthreads();

    // per-k hoisted weight terms: sc = lmax/Lp, tf = (lmax-Lp)/Lp
    const float lmaxf = s_lmax;
#pragma unroll
    for (int i = 0; i < 4; i++) {
        int k = base + i;
        if (i < EPT && k < K) {
            const float Lp = s_Lp[k];
            s_sc[k] = __fdiv_rn(lmaxf, Lp);
            s_tf[k] = __fdiv_rn(__fadd_rn(lmaxf, -Lp), Lp);
        }
    }
    __syncthreads();

    // ---------------- (k, w) for this thread's 4 columns ----------------
    const int tt0 = (blockIdx.x * blockDim.x + threadIdx.x) * 4;
    if (tt0 >= T) return;

    const int   total = s_total;
    const bool  pow2  = (T & (T - 1)) == 0;
    const int   shift = __ffs(T) - 1;
    const double ratio = (double)total / (double)T;

    float4 w;
    int4   kk;
    float* wv = &w.x;
    int*   kv = &kk.x;

#pragma unroll
    for (int i = 0; i < 4; i++) {
        int tt = tt0 + i;
        if (tt > T - 1) tt = T - 1;

        long long slot;
        if (pow2) {
            slot = ((long long)tt * (long long)total) >> shift;  // exact
        } else {
            slot = (long long)floor((double)tt * ratio);
        }
        if (slot > (long long)(total - 1)) slot = total - 1;
        if (slot < 0) slot = 0;

        int lo = 0, hi = K;
        const int si = (int)slot;
        while (hi - lo > 1) {
            int mid = (lo + hi) >> 1;
            if (s_cum[mid] <= si) lo = mid; else hi = mid;
        }
        const int k = lo;
        const int j = si - s_cum[k];

        const float x  = __fadd_rn(__fdiv_rn(__fadd_rn(__fmul_rn(2.0f, (float)j), 1.0f), lmaxf), -1.0f);
        const float xs = __fadd_rn(__fmul_rn(s_sc[k], x), s_tf[k]);
        const float p  = __fmul_rn(__fadd_rn(__fmul_rn(__fadd_rn(xs, 1.0f), 100.0f), -1.0f), 0.5f);
        const float p0 = floorf(p);
        const float w1 = __fadd_rn(p, -p0);
        const float in0 = (p0 >=  0.0f && p0 <= 99.0f) ? 1.0f : 0.0f;
        const float in1 = (p0 >= -1.0f && p0 <= 98.0f) ? 1.0f : 0.0f;
        wv[i] = __fadd_rn(__fmul_rn(__fadd_rn(1.0f, -w1), in0), __fmul_rn(w1, in1));
        kv[i] = k;
    }

    // ---------------- fill CPB c-rows ----------------
    const int c0 = blockIdx.y * CPB;
    int c1 = c0 + CPB;
    if (c1 > C) c1 = C;

    const bool vec  = (tt0 + 3 < T);
    const bool same = (kk.x == kk.w);   // k monotone: ends equal => all equal

    if (same & vec) {
        const float* Ap = A + (size_t)c0 * (size_t)K + kk.x;
        float* op = out + (size_t)c0 * (size_t)T + tt0;
#pragma unroll 4
        for (int c = c0; c < c1; ++c) {
            const float a = __ldg(Ap);
            float4 o = make_float4(a * w.x, a * w.y, a * w.z, a * w.w);
            __stcs(reinterpret_cast<float4*>(op), o);
            Ap += K;
            op += T;
        }
    } else {
        for (int c = c0; c < c1; ++c) {
            const float* Ar = A + (size_t)c * (size_t)K;
            float4 o;
            o.x = __ldg(Ar + kk.x) * w.x;
            o.y = __ldg(Ar + kk.y) * w.y;
            o.z = __ldg(Ar + kk.z) * w.z;
            o.w = __ldg(Ar + kk.w) * w.w;
            float* op = out + (size_t)c * (size_t)T + tt0;
            if (vec) {
                __stcs(reinterpret_cast<float4*>(op), o);
            } else {
                if (tt0     < T) op[0] = o.x;
                if (tt0 + 1 < T) op[1] = o.y;
                if (tt0 + 2 < T) op[2] = o.z;
                if (tt0 + 3 < T) op[3] = o.w;
            }
        }
    }
}

// ---------------------------------------------------------------------------
extern "C" void kernel_launch(void* const* d_in, const int* in_sizes, int n_in,
                              void* d_out, int out_size)
{
    const float* A = (const float*)d_in[0];   // [C, K]
    const float* L = (const float*)d_in[1];   // [K]

    const int K = in_sizes[1];
    const int C = in_sizes[0] / K;
    const int T = out_size / C;               // out is [1, C, T]

    const int cols_per_block = 256 * 4;
    const int gx = (T + cols_per_block - 1) / cols_per_block;

    dim3 grid(gx, (C + CPB - 1) / CPB);
    fused_kernel<<<grid, 256>>>(L, A, (float*)d_out, K, T, C, (float)T);
}